// round 7
// baseline (speedup 1.0000x reference)
#include <cuda_runtime.h>
#include <cuda_bf16.h>

#define GRID_N 4
#define WIN    3
#define NWIN   (GRID_N - WIN + 1)   // 2
#define NCELL  (GRID_N * GRID_N)    // 16
#define B_MAX  4096

// Per-(batch, cell) sums + per-batch arrival counters.
// Device globals (no allocs). g_cnt is zero-initialized at load and each
// kernel run returns it to 0 (last block resets) -> graph-replay invariant.
__device__ float        g_cell[B_MAX * NCELL];
__device__ unsigned int g_cnt[B_MAX];

// ---------------- Fast path: H = W = 512 ----------------
// Grid: B*4 CTAs, 256 threads. CTA (b, gy) reduces one 128-row stripe
// (16384 float4). Thread t reads float4 i = k*256 + t; i & 127 == t & 127,
// so grid-col group gx = (t>>5)&3 is constant per thread, uniform per warp.
// Warp w (0..7) owns gx = w&3 -> cell sum = wsum[gx] + wsum[gx+4].
// Last CTA to finish a batch does window sums + argmax (float out).
__global__ __launch_bounds__(256) void stripe_kernel(
        const float4* __restrict__ in, float* __restrict__ out) {
    int blk = blockIdx.x;
    int gy  = blk & 3;
    int b   = blk >> 2;

    const float4* base = in + (size_t)b * 65536 + (size_t)gy * 16384;

    int t = threadIdx.x;
    float acc = 0.0f;
#pragma unroll 16
    for (int k = 0; k < 64; k++) {
        float4 v = base[k * 256 + t];
        acc += (v.x + v.y) + (v.z + v.w);
    }

#pragma unroll
    for (int o = 16; o > 0; o >>= 1)
        acc += __shfl_down_sync(0xffffffffu, acc, o);

    __shared__ float wsum[8];
    if ((t & 31) == 0) wsum[t >> 5] = acc;
    __syncthreads();

    __shared__ unsigned int s_last;
    if (t == 0) {
        // Single writer for this stripe's 4 cells: no zeroing, no atomics.
#pragma unroll
        for (int gx = 0; gx < 4; gx++)
            g_cell[b * NCELL + gy * 4 + gx] = wsum[gx] + wsum[gx + 4];
        __threadfence();                       // publish before arrival
        s_last = atomicAdd(&g_cnt[b], 1u);     // 0..3
    }
    __syncthreads();

    if (t == 0 && s_last == 3u) {
        __threadfence();                       // acquire side
        float c[NCELL];
#pragma unroll
        for (int i = 0; i < NCELL; i++)
            c[i] = __ldcg(&g_cell[b * NCELL + i]);  // L2-coherent reads

        float win[NWIN * NWIN];
#pragma unroll
        for (int r = 0; r < NWIN; r++)
#pragma unroll
            for (int q = 0; q < NWIN; q++) {
                float s = 0.0f;
#pragma unroll
                for (int dr = 0; dr < WIN; dr++)
#pragma unroll
                    for (int dc = 0; dc < WIN; dc++)
                        s += c[(r + dr) * GRID_N + (q + dc)];
                win[r * NWIN + q] = s;
            }
        float best = win[0];
        int bi = 0;
#pragma unroll
        for (int k = 1; k < NWIN * NWIN; k++)
            if (win[k] > best) { best = win[k]; bi = k; }

        out[b * 2 + 0] = (float)(bi >> 1);     // row (float32 output!)
        out[b * 2 + 1] = (float)(bi & 1);      // col

        g_cnt[b] = 0u;                         // reset for next graph replay
    }
}

// ---------------- Generic fallback (any square H=W, divisible by 4) --------
__global__ __launch_bounds__(256) void cell_sum_kernel(
        const float* __restrict__ in, int HW, int W, int gh, int gw) {
    int blk  = blockIdx.x;
    int cell = blk & (NCELL - 1);
    int b    = blk >> 4;
    int gx = cell & (GRID_N - 1);
    int gy = cell >> 2;

    const float* base = in + (size_t)b * HW + (size_t)(gy * gh) * W + (size_t)gx * gw;

    int t = threadIdx.x;
    int n = gh * gw;
    float acc = 0.0f;
    for (int i = t; i < n; i += 256) {
        int r = i / gw;
        int c = i - r * gw;
        acc += base[(size_t)r * W + c];
    }
    __shared__ float sh[256];
    sh[t] = acc;
    __syncthreads();
#pragma unroll
    for (int s = 128; s > 0; s >>= 1) {
        if (t < s) sh[t] += sh[t + s];
        __syncthreads();
    }
    if (t == 0) g_cell[blk] = sh[0];
}

__global__ void select_kernel(float* __restrict__ out, int B) {
    int b = blockIdx.x * blockDim.x + threadIdx.x;
    if (b >= B) return;
    float c[NCELL];
#pragma unroll
    for (int i = 0; i < NCELL; i++) c[i] = g_cell[b * NCELL + i];

    float win[NWIN * NWIN];
#pragma unroll
    for (int r = 0; r < NWIN; r++)
#pragma unroll
        for (int q = 0; q < NWIN; q++) {
            float s = 0.0f;
#pragma unroll
            for (int dr = 0; dr < WIN; dr++)
#pragma unroll
                for (int dc = 0; dc < WIN; dc++)
                    s += c[(r + dr) * GRID_N + (q + dc)];
            win[r * NWIN + q] = s;
        }
    float best = win[0];
    int bi = 0;
#pragma unroll
    for (int k = 1; k < NWIN * NWIN; k++)
        if (win[k] > best) { best = win[k]; bi = k; }

    out[b * 2 + 0] = (float)(bi / NWIN);
    out[b * 2 + 1] = (float)(bi % NWIN);
}

extern "C" void kernel_launch(void* const* d_in, const int* in_sizes, int n_in,
                              void* d_out, int out_size) {
    int best_i = 0;
    for (int i = 1; i < n_in; i++)
        if (in_sizes[i] > in_sizes[best_i]) best_i = i;
    const float* in = (const float*)d_in[best_i];
    float* out = (float*)d_out;

    int B = out_size / 2;
    if (B < 1) B = 1;
    if (B > B_MAX) B = B_MAX;
    long long HW = (long long)in_sizes[best_i] / B;

    if (HW == 512LL * 512LL) {
        stripe_kernel<<<B * 4, 256>>>((const float4*)in, out);
    } else {
        int H = 1;
        while ((long long)(H + 1) * (H + 1) <= HW) H++;
        int W = H;
        cell_sum_kernel<<<B * NCELL, 256>>>(in, (int)HW, W, H / GRID_N, W / GRID_N);
        select_kernel<<<(B + 127) / 128, 128>>>(out, B);
    }
}